// round 8
// baseline (speedup 1.0000x reference)
#include <cuda_runtime.h>
#include <math.h>
#include <stdint.h>

#define NP 8732
#define NC 21
#define NB 128
#define NO 32
#define TPB 512
#define PPT 18           // ceil(8732/512) = 18 (512*18 = 9216)
#define THRESH 0.5f
#define ALPHA 10.0

// per-block outputs (written every launch -> no init kernel needed)
__device__ double g_hard[NB];
__device__ double g_loc[NB];
__device__ double g_cp[NB];
__device__ int    g_np[NB];

__global__ __launch_bounds__(TPB, 1)
void fused_k(const float* __restrict__ pred_loc,
             const float* __restrict__ pred_cls,
             const float* __restrict__ b_boxes,
             const int*   __restrict__ b_labels,
             const float* __restrict__ priors) {
    const int b    = blockIdx.x;
    const int tid  = threadIdx.x;
    const int lane = tid & 31;
    const int wid  = tid >> 5;     // 0..15

    __shared__ float sce[NP];                 // 34928 B: CE of negatives
    __shared__ unsigned char sov[NP];         //  8732 B: force-match object per prior
    __shared__ float sbx1[NO], sby1[NO], sbx2[NO], sby2[NO], sba[NO];
    __shared__ int   slab[NO];
    __shared__ int   sbest[NO];
    __shared__ float swv[4][16];
    __shared__ int   swi[4][16];
    __shared__ int   sscnt[32];               // one counter per radix pass
    __shared__ int   snpos;
    __shared__ int    siw[16];
    __shared__ double sdw[16];
    __shared__ double sdw2[16];

    if (tid < NO) {
        const float* bb = b_boxes + ((size_t)b * NO + tid) * 4;
        float x1 = bb[0], y1 = bb[1], x2 = bb[2], y2 = bb[3];
        sbx1[tid] = x1; sby1[tid] = y1; sbx2[tid] = x2; sby2[tid] = y2;
        sba[tid]  = (x2 - x1) * (y2 - y1);
        slab[tid] = b_labels[b * NO + tid];
    }
    if (tid < 32) sscnt[tid] = 0;
    #pragma unroll
    for (int i = 0; i < PPT; i++) {
        int p = tid + i * TPB;
        if (p < NP) sov[p] = 255;
    }
    __syncthreads();

    // ---------------- Phase A: single IoU pass ----------------
    float pbv[PPT]; int pbm[PPT];
    #pragma unroll
    for (int i = 0; i < PPT; i++) { pbv[i] = -1.0f; pbm[i] = 0; }

    for (int g = 0; g < NO / 4; ++g) {
        float B1[4], B2[4], B3[4], B4[4], BA[4];
        #pragma unroll
        for (int j = 0; j < 4; j++) {
            int m = g * 4 + j;
            B1[j] = sbx1[m]; B2[j] = sby1[m];
            B3[j] = sbx2[m]; B4[j] = sby2[m]; BA[j] = sba[m];
        }
        float obv[4]; int obi[4];
        #pragma unroll
        for (int j = 0; j < 4; j++) { obv[j] = -1.0f; obi[j] = 0x7fffffff; }

        #pragma unroll
        for (int i = 0; i < PPT; i++) {
            int p = tid + i * TPB;
            if (p < NP) {
                float4 pc = reinterpret_cast<const float4*>(priors)[p];
                float hw  = pc.z * 0.5f, hh = pc.w * 0.5f;
                float px1 = pc.x - hw, py1 = pc.y - hh;
                float px2 = pc.x + hw, py2 = pc.y + hh;
                float pa  = (px2 - px1) * (py2 - py1);
                #pragma unroll
                for (int j = 0; j < 4; j++) {
                    float ix1 = fmaxf(B1[j], px1), iy1 = fmaxf(B2[j], py1);
                    float ix2 = fminf(B3[j], px2), iy2 = fminf(B4[j], py2);
                    float iw  = fmaxf(ix2 - ix1, 0.0f);
                    float ih  = fmaxf(iy2 - iy1, 0.0f);
                    float inter = iw * ih;
                    float uni   = (BA[j] + pa) - inter;
                    float iou   = __fdividef(inter, uni);     // rcp+mul
                    if (iou > pbv[i]) { pbv[i] = iou; pbm[i] = g * 4 + j; }
                    if (iou > obv[j]) { obv[j] = iou; obi[j] = p; }
                }
            }
        }
        // block argmax for the 4 objects of this group (min index on ties)
        #pragma unroll
        for (int j = 0; j < 4; j++) {
            float v = obv[j]; int ix = obi[j];
            #pragma unroll
            for (int o = 16; o > 0; o >>= 1) {
                float v2 = __shfl_down_sync(0xffffffffu, v, o);
                int   i2 = __shfl_down_sync(0xffffffffu, ix, o);
                if (v2 > v || (v2 == v && i2 < ix)) { v = v2; ix = i2; }
            }
            if (lane == 0) { swv[j][wid] = v; swi[j][wid] = ix; }
        }
        __syncthreads();
        if (wid < 4 && lane < 16) {
            float v = swv[wid][lane]; int ix = swi[wid][lane];
            #pragma unroll
            for (int o = 8; o > 0; o >>= 1) {
                float v2 = __shfl_down_sync(0xffffu, v, o);
                int   i2 = __shfl_down_sync(0xffffu, ix, o);
                if (v2 > v || (v2 == v && i2 < ix)) { v = v2; ix = i2; }
            }
            if (lane == 0) sbest[g * 4 + wid] = ix;
        }
        __syncthreads();
    }

    // min object per overridden prior (descending m -> smallest m wins)
    if (tid == 0) {
        for (int m = NO - 1; m >= 0; --m) sov[sbest[m]] = (unsigned char)m;
    }
    __syncthreads();

    // ---------------- Phase B: matching fix-up + CE + loc ----------------
    int    npl  = 0;
    double cpl  = 0.0;
    double locl = 0.0;

    #pragma unroll
    for (int i = 0; i < PPT; i++) {
        int p = tid + i * TPB;
        if (p < NP) {
            float bv = pbv[i]; int bm = pbm[i];
            int ov = sov[p];
            if (ov != 255) {
                if (bv < 1.0f || (bv == 1.0f && ov < bm)) { bv = 1.0f; bm = ov; }
            }
            bool pos = (bv >= THRESH);
            int  cls = pos ? slab[bm] : 0;

            const float* lg = pred_cls + ((size_t)b * NP + p) * NC;
            float se = 0.0f, lc = 0.0f;
            #pragma unroll
            for (int c = 0; c < NC; c++) {
                float v = lg[c];
                se += __expf(v);          // logits ~N(0,1): no overflow risk
                if (c == cls) lc = v;
            }
            float ce = __logf(se) - lc;

            if (pos) {
                sce[p] = 0.0f;
                npl++;
                cpl += (double)ce;
                float4 pc = reinterpret_cast<const float4*>(priors)[p];
                float x1 = sbx1[bm], y1 = sby1[bm], x2 = sbx2[bm], y2 = sby2[bm];
                float cx = (x1 + x2) * 0.5f, cy = (y1 + y2) * 0.5f;
                float bw = x2 - x1, bh = y2 - y1;
                float gx = (cx - pc.x) / (pc.z / 10.0f);
                float gy = (cy - pc.y) / (pc.w / 10.0f);
                float gw = __logf(bw / pc.z) * 5.0f;
                float gh = __logf(bh / pc.w) * 5.0f;
                float4 pl = reinterpret_cast<const float4*>(pred_loc)[(size_t)b * NP + p];
                locl += (double)(fabsf(pl.x - gx) + fabsf(pl.y - gy) +
                                 fabsf(pl.z - gw) + fabsf(pl.w - gh));
            } else {
                sce[p] = fmaxf(ce, 0.0f);   // guard tiny negatives
            }
        }
    }

    // block reduce npos / conf_pos / loc
    #pragma unroll
    for (int o = 16; o > 0; o >>= 1) {
        npl  += __shfl_down_sync(0xffffffffu, npl, o);
        cpl  += __shfl_down_sync(0xffffffffu, cpl, o);
        locl += __shfl_down_sync(0xffffffffu, locl, o);
    }
    if (lane == 0) { siw[wid] = npl; sdw[wid] = cpl; sdw2[wid] = locl; }
    __syncthreads();
    if (wid == 0 && lane < 16) {
        int n = siw[lane]; double c = sdw[lane]; double l = sdw2[lane];
        #pragma unroll
        for (int o = 8; o > 0; o >>= 1) {
            n += __shfl_down_sync(0xffffu, n, o);
            c += __shfl_down_sync(0xffffu, c, o);
            l += __shfl_down_sync(0xffffu, l, o);
        }
        if (lane == 0) { snpos = n; g_np[b] = n; g_cp[b] = c; g_loc[b] = l; }
    }
    __syncthreads();

    // ---------------- Phase C: exact top-K via radix select on smem ------
    int K = 3 * snpos;
    if (K > NP) K = NP;

    unsigned t = 0u;
    for (int bit = 30; bit >= 0; --bit) {
        unsigned cand = t | (1u << bit);
        int c = 0;
        #pragma unroll
        for (int i = 0; i < PPT; i++) {
            int p = tid + i * TPB;
            if (p < NP && __float_as_uint(sce[p]) >= cand) c++;
        }
        #pragma unroll
        for (int o = 16; o > 0; o >>= 1) c += __shfl_down_sync(0xffffffffu, c, o);
        if (lane == 0 && c) atomicAdd(&sscnt[bit], c);
        __syncthreads();
        if (sscnt[bit] >= K) t = cand;
        // next pass uses a different counter slot -> no second sync needed
    }

    int    cgt = 0;
    double sg  = 0.0;
    #pragma unroll
    for (int i = 0; i < PPT; i++) {
        int p = tid + i * TPB;
        if (p < NP) {
            unsigned v = __float_as_uint(sce[p]);
            if (v > t) { cgt++; sg += (double)__uint_as_float(v); }
        }
    }
    #pragma unroll
    for (int o = 16; o > 0; o >>= 1) {
        cgt += __shfl_down_sync(0xffffffffu, cgt, o);
        sg  += __shfl_down_sync(0xffffffffu, sg, o);
    }
    __syncthreads();            // safe reuse of siw/sdw
    if (lane == 0) { siw[wid] = cgt; sdw[wid] = sg; }
    __syncthreads();
    if (tid == 0) {
        int c = 0; double sm = 0.0;
        #pragma unroll
        for (int w = 0; w < 16; w++) { c += siw[w]; sm += sdw[w]; }
        g_hard[b] = sm + (double)(K - c) * (double)__uint_as_float(t);
    }
}

// ---------------- finalize: reduce 128 per-image slots ----------------
__global__ void finalize_k(float* __restrict__ out) {
    int tid  = threadIdx.x;           // 128 threads
    int lane = tid & 31, wid = tid >> 5;
    double h = g_hard[tid] + g_cp[tid];
    double l = g_loc[tid];
    int    n = g_np[tid];
    #pragma unroll
    for (int o = 16; o > 0; o >>= 1) {
        h += __shfl_down_sync(0xffffffffu, h, o);
        l += __shfl_down_sync(0xffffffffu, l, o);
        n += __shfl_down_sync(0xffffffffu, n, o);
    }
    __shared__ double sh[4], sl[4];
    __shared__ int    sn[4];
    if (lane == 0) { sh[wid] = h; sl[wid] = l; sn[wid] = n; }
    __syncthreads();
    if (tid == 0) {
        double H = sh[0] + sh[1] + sh[2] + sh[3];
        double L = sl[0] + sl[1] + sl[2] + sl[3];
        double N = (double)(sn[0] + sn[1] + sn[2] + sn[3]);
        double loc  = ALPHA * (L / (N * 4.0));
        double conf = H / N;
        out[0] = (float)(conf + loc);
        out[1] = (float)loc;
        out[2] = (float)conf;
    }
}

extern "C" void kernel_launch(void* const* d_in, const int* in_sizes, int n_in,
                              void* d_out, int out_size) {
    const float* pred_loc = (const float*)d_in[0];
    const float* pred_cls = (const float*)d_in[1];
    const float* b_boxes  = (const float*)d_in[2];
    const int*   b_labels = (const int*)  d_in[3];
    const float* priors   = (const float*)d_in[4];
    float* out = (float*)d_out;

    fused_k<<<NB, TPB>>>(pred_loc, pred_cls, b_boxes, b_labels, priors);
    finalize_k<<<1, NB>>>(out);
}

// round 9
// speedup vs baseline: 1.0141x; 1.0141x over previous
#include <cuda_runtime.h>
#include <math.h>
#include <stdint.h>

#define NP 8732
#define NC 21
#define NB 128
#define NO 32
#define TPB 512
#define PPT 18           // ceil(8732/512) = 18 (512*18 = 9216)
#define THRESH 0.5f
#define ALPHA 10.0

// per-block outputs (written every launch -> no init kernel needed)
__device__ double g_hard[NB];
__device__ double g_loc[NB];
__device__ double g_cp[NB];
__device__ int    g_np[NB];

__global__ __launch_bounds__(TPB, 1)
void fused_k(const float* __restrict__ pred_loc,
             const float* __restrict__ pred_cls,
             const float* __restrict__ b_boxes,
             const int*   __restrict__ b_labels,
             const float* __restrict__ priors) {
    const int b    = blockIdx.x;
    const int tid  = threadIdx.x;
    const int lane = tid & 31;
    const int wid  = tid >> 5;     // 0..15

    __shared__ float sce[NP];                 // 34928 B: CE of negatives
    __shared__ unsigned char sov[NP];         //  8732 B: force-match object per prior
    __shared__ float sbx1[NO], sby1[NO], sbx2[NO], sby2[NO], sba[NO];
    __shared__ int   slab[NO];
    __shared__ int   sbest[NO];
    __shared__ float swv[4][16];
    __shared__ int   swi[4][16];
    __shared__ int   sscnt[32];               // one counter per radix pass
    __shared__ int   snpos;
    __shared__ int    siw[16];
    __shared__ double sdw[16];
    __shared__ double sdw2[16];

    if (tid < NO) {
        const float* bb = b_boxes + ((size_t)b * NO + tid) * 4;
        float x1 = bb[0], y1 = bb[1], x2 = bb[2], y2 = bb[3];
        sbx1[tid] = x1; sby1[tid] = y1; sbx2[tid] = x2; sby2[tid] = y2;
        sba[tid]  = (x2 - x1) * (y2 - y1);
        slab[tid] = b_labels[b * NO + tid];
    }
    if (tid < 32) sscnt[tid] = 0;
    #pragma unroll
    for (int i = 0; i < PPT; i++) {
        int p = tid + i * TPB;
        if (p < NP) sov[p] = 255;
    }
    __syncthreads();

    // ---------------- Phase A: single IoU pass ----------------
    float pbv[PPT]; int pbm[PPT];
    #pragma unroll
    for (int i = 0; i < PPT; i++) { pbv[i] = -1.0f; pbm[i] = 0; }

    for (int g = 0; g < NO / 4; ++g) {
        float B1[4], B2[4], B3[4], B4[4], BA[4];
        #pragma unroll
        for (int j = 0; j < 4; j++) {
            int m = g * 4 + j;
            B1[j] = sbx1[m]; B2[j] = sby1[m];
            B3[j] = sbx2[m]; B4[j] = sby2[m]; BA[j] = sba[m];
        }
        float obv[4]; int obi[4];
        #pragma unroll
        for (int j = 0; j < 4; j++) { obv[j] = -1.0f; obi[j] = 0x7fffffff; }

        #pragma unroll
        for (int i = 0; i < PPT; i++) {
            int p = tid + i * TPB;
            if (p < NP) {
                float4 pc = reinterpret_cast<const float4*>(priors)[p];
                float hw  = pc.z * 0.5f, hh = pc.w * 0.5f;
                float px1 = pc.x - hw, py1 = pc.y - hh;
                float px2 = pc.x + hw, py2 = pc.y + hh;
                float pa  = (px2 - px1) * (py2 - py1);
                #pragma unroll
                for (int j = 0; j < 4; j++) {
                    float ix1 = fmaxf(B1[j], px1), iy1 = fmaxf(B2[j], py1);
                    float ix2 = fminf(B3[j], px2), iy2 = fminf(B4[j], py2);
                    float iw  = fmaxf(ix2 - ix1, 0.0f);
                    float ih  = fmaxf(iy2 - iy1, 0.0f);
                    float inter = iw * ih;
                    float uni   = (BA[j] + pa) - inter;
                    float iou   = __fdividef(inter, uni);     // rcp+mul
                    if (iou > pbv[i]) { pbv[i] = iou; pbm[i] = g * 4 + j; }
                    if (iou > obv[j]) { obv[j] = iou; obi[j] = p; }
                }
            }
        }
        // block argmax for the 4 objects of this group (min index on ties)
        #pragma unroll
        for (int j = 0; j < 4; j++) {
            float v = obv[j]; int ix = obi[j];
            #pragma unroll
            for (int o = 16; o > 0; o >>= 1) {
                float v2 = __shfl_down_sync(0xffffffffu, v, o);
                int   i2 = __shfl_down_sync(0xffffffffu, ix, o);
                if (v2 > v || (v2 == v && i2 < ix)) { v = v2; ix = i2; }
            }
            if (lane == 0) { swv[j][wid] = v; swi[j][wid] = ix; }
        }
        __syncthreads();
        if (wid < 4 && lane < 16) {
            float v = swv[wid][lane]; int ix = swi[wid][lane];
            #pragma unroll
            for (int o = 8; o > 0; o >>= 1) {
                float v2 = __shfl_down_sync(0xffffu, v, o);
                int   i2 = __shfl_down_sync(0xffffu, ix, o);
                if (v2 > v || (v2 == v && i2 < ix)) { v = v2; ix = i2; }
            }
            if (lane == 0) sbest[g * 4 + wid] = ix;
        }
        __syncthreads();
    }

    // min object per overridden prior (descending m -> smallest m wins)
    if (tid == 0) {
        for (int m = NO - 1; m >= 0; --m) sov[sbest[m]] = (unsigned char)m;
    }
    __syncthreads();

    // ---------------- Phase B: matching fix-up + CE + loc ----------------
    int    npl  = 0;
    double cpl  = 0.0;
    double locl = 0.0;

    #pragma unroll
    for (int i = 0; i < PPT; i++) {
        int p = tid + i * TPB;
        if (p < NP) {
            float bv = pbv[i]; int bm = pbm[i];
            int ov = sov[p];
            if (ov != 255) {
                if (bv < 1.0f || (bv == 1.0f && ov < bm)) { bv = 1.0f; bm = ov; }
            }
            bool pos = (bv >= THRESH);
            int  cls = pos ? slab[bm] : 0;

            const float* lg = pred_cls + ((size_t)b * NP + p) * NC;
            float se = 0.0f, lc = 0.0f;
            #pragma unroll
            for (int c = 0; c < NC; c++) {
                float v = lg[c];
                se += __expf(v);          // logits ~N(0,1): no overflow risk
                if (c == cls) lc = v;
            }
            float ce = __logf(se) - lc;

            if (pos) {
                sce[p] = 0.0f;
                npl++;
                cpl += (double)ce;
                float4 pc = reinterpret_cast<const float4*>(priors)[p];
                float x1 = sbx1[bm], y1 = sby1[bm], x2 = sbx2[bm], y2 = sby2[bm];
                float cx = (x1 + x2) * 0.5f, cy = (y1 + y2) * 0.5f;
                float bw = x2 - x1, bh = y2 - y1;
                float gx = (cx - pc.x) / (pc.z / 10.0f);
                float gy = (cy - pc.y) / (pc.w / 10.0f);
                float gw = __logf(bw / pc.z) * 5.0f;
                float gh = __logf(bh / pc.w) * 5.0f;
                float4 pl = reinterpret_cast<const float4*>(pred_loc)[(size_t)b * NP + p];
                locl += (double)(fabsf(pl.x - gx) + fabsf(pl.y - gy) +
                                 fabsf(pl.z - gw) + fabsf(pl.w - gh));
            } else {
                sce[p] = fmaxf(ce, 0.0f);   // guard tiny negatives
            }
        }
    }

    // block reduce npos / conf_pos / loc
    #pragma unroll
    for (int o = 16; o > 0; o >>= 1) {
        npl  += __shfl_down_sync(0xffffffffu, npl, o);
        cpl  += __shfl_down_sync(0xffffffffu, cpl, o);
        locl += __shfl_down_sync(0xffffffffu, locl, o);
    }
    if (lane == 0) { siw[wid] = npl; sdw[wid] = cpl; sdw2[wid] = locl; }
    __syncthreads();
    if (wid == 0 && lane < 16) {
        int n = siw[lane]; double c = sdw[lane]; double l = sdw2[lane];
        #pragma unroll
        for (int o = 8; o > 0; o >>= 1) {
            n += __shfl_down_sync(0xffffu, n, o);
            c += __shfl_down_sync(0xffffu, c, o);
            l += __shfl_down_sync(0xffffu, l, o);
        }
        if (lane == 0) { snpos = n; g_np[b] = n; g_cp[b] = c; g_loc[b] = l; }
    }
    __syncthreads();

    // ---------------- Phase C: exact top-K via radix select on smem ------
    int K = 3 * snpos;
    if (K > NP) K = NP;

    unsigned t = 0u;
    for (int bit = 30; bit >= 0; --bit) {
        unsigned cand = t | (1u << bit);
        int c = 0;
        #pragma unroll
        for (int i = 0; i < PPT; i++) {
            int p = tid + i * TPB;
            if (p < NP && __float_as_uint(sce[p]) >= cand) c++;
        }
        #pragma unroll
        for (int o = 16; o > 0; o >>= 1) c += __shfl_down_sync(0xffffffffu, c, o);
        if (lane == 0 && c) atomicAdd(&sscnt[bit], c);
        __syncthreads();
        if (sscnt[bit] >= K) t = cand;
        // next pass uses a different counter slot -> no second sync needed
    }

    int    cgt = 0;
    double sg  = 0.0;
    #pragma unroll
    for (int i = 0; i < PPT; i++) {
        int p = tid + i * TPB;
        if (p < NP) {
            unsigned v = __float_as_uint(sce[p]);
            if (v > t) { cgt++; sg += (double)__uint_as_float(v); }
        }
    }
    #pragma unroll
    for (int o = 16; o > 0; o >>= 1) {
        cgt += __shfl_down_sync(0xffffffffu, cgt, o);
        sg  += __shfl_down_sync(0xffffffffu, sg, o);
    }
    __syncthreads();            // safe reuse of siw/sdw
    if (lane == 0) { siw[wid] = cgt; sdw[wid] = sg; }
    __syncthreads();
    if (tid == 0) {
        int c = 0; double sm = 0.0;
        #pragma unroll
        for (int w = 0; w < 16; w++) { c += siw[w]; sm += sdw[w]; }
        g_hard[b] = sm + (double)(K - c) * (double)__uint_as_float(t);
    }
}

// ---------------- finalize: reduce 128 per-image slots ----------------
__global__ void finalize_k(float* __restrict__ out) {
    int tid  = threadIdx.x;           // 128 threads
    int lane = tid & 31, wid = tid >> 5;
    double h = g_hard[tid] + g_cp[tid];
    double l = g_loc[tid];
    int    n = g_np[tid];
    #pragma unroll
    for (int o = 16; o > 0; o >>= 1) {
        h += __shfl_down_sync(0xffffffffu, h, o);
        l += __shfl_down_sync(0xffffffffu, l, o);
        n += __shfl_down_sync(0xffffffffu, n, o);
    }
    __shared__ double sh[4], sl[4];
    __shared__ int    sn[4];
    if (lane == 0) { sh[wid] = h; sl[wid] = l; sn[wid] = n; }
    __syncthreads();
    if (tid == 0) {
        double H = sh[0] + sh[1] + sh[2] + sh[3];
        double L = sl[0] + sl[1] + sl[2] + sl[3];
        double N = (double)(sn[0] + sn[1] + sn[2] + sn[3]);
        double loc  = ALPHA * (L / (N * 4.0));
        double conf = H / N;
        out[0] = (float)(conf + loc);
        out[1] = (float)loc;
        out[2] = (float)conf;
    }
}

extern "C" void kernel_launch(void* const* d_in, const int* in_sizes, int n_in,
                              void* d_out, int out_size) {
    const float* pred_loc = (const float*)d_in[0];
    const float* pred_cls = (const float*)d_in[1];
    const float* b_boxes  = (const float*)d_in[2];
    const int*   b_labels = (const int*)  d_in[3];
    const float* priors   = (const float*)d_in[4];
    float* out = (float*)d_out;

    fused_k<<<NB, TPB>>>(pred_loc, pred_cls, b_boxes, b_labels, priors);
    finalize_k<<<1, NB>>>(out);
}